// round 10
// baseline (speedup 1.0000x reference)
#include <cuda_runtime.h>
#include <cuda_bf16.h>

#define NN 100000
#define NE 1250000
#define DD 64
#define K_ITERS 5
#define EPSF 1e-8f
#define NB_NODE 391            // ceil(NN/256)
#define FEAT_BLOCKS 3125       // NN/32 exactly
#define CNT_BLOCKS 4883        // ceil(NE/256)

// Scratch (device globals — allocation-free).
__device__ __align__(16) float g_hn[NN * DD]; // normalized tanh features
__device__ float g_dis[NN];     // deg^{-1/2}
__device__ float g_f[NN];       // propagation ping
__device__ float g_f2[NN];      // propagation pong
__device__ float g_f0[NN];      // relu(mask)
// CSR by destination
__device__ int   g_cnt[NN];
__device__ int   g_off[NN];
__device__ int   g_cur[NN];
__device__ int   g_part[512];
__device__ __align__(8) int2 g_csr[NE];   // .x = src, .y = float bits of weight
__device__ int   g_ceid[NE];    // slot -> original edge id (for ew output)

// ---------------------------------------------------------------------------
// Mega kernel 1: feature transform (blocks < FEAT_BLOCKS) + in-degree count
// (remaining blocks). The two halves are independent.
// ---------------------------------------------------------------------------
__global__ void k_feat_cnt(const float* __restrict__ x, const float* __restrict__ W,
                           const float* __restrict__ b, const int* __restrict__ ei) {
    if (blockIdx.x >= FEAT_BLOCKS) {
        // ---- in-degree counting ----
        int e = (blockIdx.x - FEAT_BLOCKS) * 256 + threadIdx.x;
        if (e < NE) atomicAdd(&g_cnt[ei[NE + e]], 1);
        return;
    }

    __shared__ float Wt[DD][DD + 1];   // Wt[k][j] = W[j][k]
    __shared__ float xs[32][DD];
    __shared__ float bs[DD];

    int tid = threadIdx.x;
    int row0 = blockIdx.x * 32;

    for (int i = tid; i < DD * DD; i += 256) {
        int j = i >> 6, k = i & 63;
        Wt[k][j] = W[i];
    }
    if (tid < DD) bs[tid] = b[tid];
    for (int i = tid; i < 32 * DD; i += 256) {
        int r = i >> 6, k = i & 63;
        xs[r][k] = x[(row0 + r) * DD + k];
    }
    __syncthreads();

    int warp = tid >> 5, lane = tid & 31;
    int rbase = warp * 4;

    float acc[4][2];
#pragma unroll
    for (int r = 0; r < 4; r++) {
        acc[r][0] = bs[lane];
        acc[r][1] = bs[lane + 32];
    }

#pragma unroll 8
    for (int k = 0; k < DD; k++) {
        float w0 = Wt[k][lane];
        float w1 = Wt[k][lane + 32];
#pragma unroll
        for (int r = 0; r < 4; r++) {
            float xv = xs[rbase + r][k];
            acc[r][0] = fmaf(xv, w0, acc[r][0]);
            acc[r][1] = fmaf(xv, w1, acc[r][1]);
        }
    }

#pragma unroll
    for (int r = 0; r < 4; r++) {
        int n = row0 + rbase + r;
        float a0 = tanhf(acc[r][0]);
        float a1 = tanhf(acc[r][1]);
        float ss = a0 * a0 + a1 * a1;
#pragma unroll
        for (int o = 16; o; o >>= 1) ss += __shfl_xor_sync(0xffffffffu, ss, o);
        float inv = 1.0f / fmaxf(sqrtf(ss), EPSF);
        g_hn[n * DD + lane]      = a0 * inv;
        g_hn[n * DD + lane + 32] = a1 * inv;
    }
}

// ---------------------------------------------------------------------------
// K_init: cnt = 0, f0 = relu(mask), f = f0   (must precede k_feat_cnt)
// ---------------------------------------------------------------------------
__global__ void k_init(const float* __restrict__ mask) {
    int n = blockIdx.x * blockDim.x + threadIdx.x;
    if (n < NN) {
        g_cnt[n] = 0;
        float f0 = fmaxf(mask[n], 0.0f);
        g_f0[n] = f0;
        g_f[n]  = f0;
    }
}

// ---------------------------------------------------------------------------
// CSR build: block sums -> inclusive scan of partials -> local scan + base.
// ---------------------------------------------------------------------------
__global__ void k_blocksum() {
    __shared__ int sh[256];
    int t = threadIdx.x;
    int n = blockIdx.x * 256 + t;
    sh[t] = (n < NN) ? g_cnt[n] : 0;
    __syncthreads();
    for (int o = 128; o; o >>= 1) {
        if (t < o) sh[t] += sh[t + o];
        __syncthreads();
    }
    if (t == 0) g_part[blockIdx.x] = sh[0];
}

__global__ void k_scanpart() {   // 1 block: g_part <- INCLUSIVE scan
    __shared__ int sh[512];
    int t = threadIdx.x;
    sh[t] = (t < NB_NODE) ? g_part[t] : 0;
    __syncthreads();
    for (int o = 1; o < 512; o <<= 1) {
        int v = (t >= o) ? sh[t - o] : 0;
        __syncthreads();
        if (t >= o) sh[t] += v;
        __syncthreads();
    }
    if (t < NB_NODE) g_part[t] = sh[t];
}

__global__ void k_scanfinal() {
    __shared__ int sh[256];
    int t = threadIdx.x;
    int n = blockIdx.x * 256 + t;
    int v = (n < NN) ? g_cnt[n] : 0;
    sh[t] = v;
    __syncthreads();
    for (int o = 1; o < 256; o <<= 1) {
        int u = (t >= o) ? sh[t - o] : 0;
        __syncthreads();
        if (t >= o) sh[t] += u;
        __syncthreads();
    }
    if (n < NN) {
        int off = ((blockIdx.x > 0) ? g_part[blockIdx.x - 1] : 0) + sh[t] - v;
        g_off[n] = off;
        g_cur[n] = off;
    }
}

// ---------------------------------------------------------------------------
// Scatter edges into CSR slots (src + edge id only; weight filled later).
// ---------------------------------------------------------------------------
__global__ void k_scatter(const int* __restrict__ ei) {
    int e = blockIdx.x * blockDim.x + threadIdx.x;
    if (e >= NE) return;
    int s = ei[e];
    int d = ei[NE + e];
    int pos = atomicAdd(&g_cur[d], 1);
    g_csr[pos].x = s;
    g_ceid[pos]  = e;
}

// ---------------------------------------------------------------------------
// Edge cosines over CSR: one 16-lane group per dst node. Dst row held in
// registers (float4/lane) -> only src rows stream from L2. Computes
// w = relu(cos), writes ew (scattered by edge id), csr weight, and
// dis[d] = rsqrt(1 + sum w) inline. No atomics.
// NN % 16 groups/block layout: NN*16 threads, all warps full (NN%16==0... NN=100000, groups=NN, 16 per block of 256 -> 6250 blocks exactly).
// ---------------------------------------------------------------------------
__global__ void k_edge_csr(float* __restrict__ ew_out) {
    int t = blockIdx.x * 256 + threadIdx.x;
    int n = t >> 4;          // dst node
    int sub = t & 15;
    if (n >= NN) return;

    float4 a = *(const float4*)(g_hn + n * DD + sub * 4);
    int beg = g_off[n];
    int end = beg + g_cnt[n];
    float deg = 1.0f;        // self loop

    for (int j = beg; j < end; j++) {
        int s = g_csr[j].x;
        float4 c = *(const float4*)(g_hn + s * DD + sub * 4);
        float p = a.x * c.x + a.y * c.y + a.z * c.z + a.w * c.w;
#pragma unroll
        for (int o = 8; o; o >>= 1) p += __shfl_xor_sync(0xffffffffu, p, o);
        float w = fmaxf(p, 0.0f);   // all 16 lanes hold full sum
        if (sub == 0) {
            g_csr[j].y = __float_as_int(w);
            ew_out[g_ceid[j]] = w;
        }
        deg += w;
    }
    if (sub == 0) g_dis[n] = rsqrtf(fmaxf(deg, EPSF));
}

// ---------------------------------------------------------------------------
// Normalize CSR weights in place: cw *= dis[src] * dis[dst]
// ---------------------------------------------------------------------------
__global__ void k_nw() {
    int n = blockIdx.x * blockDim.x + threadIdx.x;
    if (n >= NN) return;
    float disd = g_dis[n];
    int beg = g_off[n];
    int end = beg + g_cnt[n];
    for (int j = beg; j < end; j++) {
        int2 p = g_csr[j];
        g_csr[j].y = __float_as_int(__int_as_float(p.y) * g_dis[p.x] * disd);
    }
}

// ---------------------------------------------------------------------------
// Fused propagation step (atomic-free):
//   fout[n] = (1-a)*( fin[n]*dis^2 + sum_j w_j * fin[src_j] ) + a*f0[n]
// ---------------------------------------------------------------------------
__global__ void k_prop(const float* __restrict__ fin, float* __restrict__ fout,
                       const float* __restrict__ alpha_p) {
    int n = blockIdx.x * blockDim.x + threadIdx.x;
    if (n >= NN) return;
    float dis = g_dis[n];
    float acc = fin[n] * dis * dis;
    int beg = g_off[n];
    int end = beg + g_cnt[n];
    for (int j = beg; j < end; j++) {
        int2 p = g_csr[j];
        acc = fmaf(__int_as_float(p.y), __ldg(&fin[p.x]), acc);
    }
    float a = *alpha_p;
    fout[n] = (1.0f - a) * acc + a * g_f0[n];
}

// ---------------------------------------------------------------------------
extern "C" void kernel_launch(void* const* d_in, const int* in_sizes, int n_in,
                              void* d_out, int out_size) {
    const float* x = (const float*)d_in[0];
    const float* mask = (const float*)d_in[1];
    const int* ei = (const int*)d_in[2];
    const float* W = (const float*)d_in[3];
    const float* b = (const float*)d_in[4];
    const float* alpha = (const float*)d_in[5];
    float* out = (float*)d_out;              // [0, NN): f, [NN, NN+NE): edge_weights
    float* ew_out = out + NN;

    const int TB = 256;

    k_init<<<NB_NODE, TB>>>(mask);
    k_feat_cnt<<<FEAT_BLOCKS + CNT_BLOCKS, 256>>>(x, W, b, ei);

    k_blocksum<<<NB_NODE, 256>>>();
    k_scanpart<<<1, 512>>>();
    k_scanfinal<<<NB_NODE, 256>>>();
    k_scatter<<<(NE + TB - 1) / TB, TB>>>(ei);

    k_edge_csr<<<(NN * 16) / 256, 256>>>(ew_out);
    k_nw<<<NB_NODE, TB>>>();

    static float* p_f = nullptr;
    static float* p_f2 = nullptr;
    if (!p_f)  cudaGetSymbolAddress((void**)&p_f,  g_f);
    if (!p_f2) cudaGetSymbolAddress((void**)&p_f2, g_f2);

    const float* cur = p_f;
    float* nxt = p_f2;
    for (int it = 0; it < K_ITERS; it++) {
        float* dst = (it == K_ITERS - 1) ? out : nxt;
        k_prop<<<NB_NODE, TB>>>(cur, dst, alpha);
        const float* tmp = cur;
        cur = dst;
        nxt = (float*)tmp;
    }
}

// round 14
// speedup vs baseline: 1.0026x; 1.0026x over previous
#include <cuda_runtime.h>
#include <cuda_bf16.h>

#define NN 100000
#define NE 1250000
#define DD 64
#define K_ITERS 5
#define EPSF 1e-8f
#define GRID 148
#define TPB 1024
#define GT (GRID * TPB)          // 151552 threads
#define ESTRIDE (GT / 16)        // 9472 edges per grid-stride step
#define TILE_ROWS 96             // rows per feat tile (3 per warp, 32 warps)
#define NTILES ((NN + TILE_ROWS - 1) / TILE_ROWS)   // 1042
#define SCAN_BLOCKS 98           // ceil(NN / 1024)

// Scratch (device globals — allocation-free).
__device__ __align__(16) float g_hn[NN * DD];
__device__ float g_deg[NN];
__device__ float g_dis[NN];
__device__ float g_f[NN];
__device__ float g_f2[NN];
__device__ float g_f0[NN];
__device__ int   g_cnt[NN];
__device__ int   g_off[NN];
__device__ int   g_cur[NN];
__device__ int   g_part[SCAN_BLOCKS];
__device__ __align__(8) int2 g_csr[NE];   // .x = src, .y = float bits of normalized weight
__device__ unsigned g_bar_count;          // zero-init; returns to 0 after each barrier
__device__ unsigned g_bar_gen;            // monotonically increasing generation

// ---------------------------------------------------------------------------
// Software grid barrier. Safe: grid == 148 blocks, 1 per SM, all co-resident.
// ---------------------------------------------------------------------------
__device__ __forceinline__ void gsync() {
    __syncthreads();
    if (threadIdx.x == 0) {
        unsigned gen = atomicAdd(&g_bar_gen, 0u);   // read BEFORE arriving
        __threadfence();                             // flush this block's writes
        unsigned t = atomicAdd(&g_bar_count, 1u);
        if (t == GRID - 1) {
            atomicExch(&g_bar_count, 0u);
            __threadfence();
            atomicAdd(&g_bar_gen, 1u);               // release
        } else {
            while (atomicAdd(&g_bar_gen, 0u) == gen) __nanosleep(64);
        }
        __threadfence();
    }
    __syncthreads();
}

// ---------------------------------------------------------------------------
// The whole pipeline in one persistent kernel.
// ---------------------------------------------------------------------------
__global__ void __launch_bounds__(TPB, 1)
k_mega(const float* __restrict__ x, const float* __restrict__ mask,
       const int* __restrict__ ei, const float* __restrict__ W,
       const float* __restrict__ b, const float* __restrict__ alpha_p,
       float* __restrict__ out, float* __restrict__ ew_out) {
    __shared__ union {
        struct { float Wt[DD][DD]; float bs[DD]; float xs[TILE_ROWS][DD]; } feat;
        int scan[TPB];
    } sm;

    const int tid  = threadIdx.x;
    const int gtid = blockIdx.x * TPB + tid;
    const int warp = tid >> 5;
    const int lane = tid & 31;

    // ---- Phase 1: init: deg=1, cnt=0, f0=relu(mask), f=f0 -----------------
    for (int n = gtid; n < NN; n += GT) {
        g_deg[n] = 1.0f;
        g_cnt[n] = 0;
        float f0 = fmaxf(mask[n], 0.0f);
        g_f0[n] = f0;
        g_f[n]  = f0;
    }
    gsync();

    // ---- Phase 2: feature transform + in-degree count ---------------------
    // Stage W transposed + b once per block.
    for (int i = tid; i < DD * DD; i += TPB) {
        int j = i >> 6, k = i & 63;
        sm.feat.Wt[k][j] = W[i];
    }
    if (tid < DD) sm.feat.bs[tid] = b[tid];
    __syncthreads();

    for (int tile = blockIdx.x; tile < NTILES; tile += GRID) {
        int row0 = tile * TILE_ROWS;
        for (int i = tid; i < TILE_ROWS * DD; i += TPB) {
            int r = i >> 6, k = i & 63;
            int n = row0 + r;
            sm.feat.xs[r][k] = (n < NN) ? x[n * DD + k] : 0.0f;
        }
        __syncthreads();

        int rbase = warp * 3;
        float acc[3][2];
#pragma unroll
        for (int r = 0; r < 3; r++) {
            acc[r][0] = sm.feat.bs[lane];
            acc[r][1] = sm.feat.bs[lane + 32];
        }
#pragma unroll 8
        for (int k = 0; k < DD; k++) {
            float w0 = sm.feat.Wt[k][lane];
            float w1 = sm.feat.Wt[k][lane + 32];
#pragma unroll
            for (int r = 0; r < 3; r++) {
                float xv = sm.feat.xs[rbase + r][k];
                acc[r][0] = fmaf(xv, w0, acc[r][0]);
                acc[r][1] = fmaf(xv, w1, acc[r][1]);
            }
        }
#pragma unroll
        for (int r = 0; r < 3; r++) {
            int n = row0 + rbase + r;
            float a0 = tanhf(acc[r][0]);
            float a1 = tanhf(acc[r][1]);
            float ss = a0 * a0 + a1 * a1;
#pragma unroll
            for (int o = 16; o; o >>= 1) ss += __shfl_xor_sync(0xffffffffu, ss, o);
            float inv = 1.0f / fmaxf(sqrtf(ss), EPSF);
            if (n < NN) {
                g_hn[n * DD + lane]      = a0 * inv;
                g_hn[n * DD + lane + 32] = a1 * inv;
            }
        }
        __syncthreads();
    }

    // In-degree counts (flat, spread int atomics)
    for (int e = gtid; e < NE; e += GT)
        atomicAdd(&g_cnt[ei[NE + e]], 1);
    gsync();

    // ---- Phase 3: block-local inclusive scan (1024 nodes / scan-block) ----
    {
        int bscan = blockIdx.x;
        int n = bscan * TPB + tid;
        int v = (bscan < SCAN_BLOCKS && n < NN) ? g_cnt[n] : 0;
        sm.scan[tid] = v;
        __syncthreads();
        for (int o = 1; o < TPB; o <<= 1) {
            int u = (tid >= o) ? sm.scan[tid - o] : 0;
            __syncthreads();
            if (tid >= o) sm.scan[tid] += u;
            __syncthreads();
        }
        if (bscan < SCAN_BLOCKS) {
            if (n < NN) g_off[n] = sm.scan[tid];        // inclusive, local
            if (tid == TPB - 1) g_part[bscan] = sm.scan[tid];
        }
    }
    gsync();

    // ---- Phase 4: block0/thr0 scans partials; ALL: flat edge cosines ------
    if (blockIdx.x == 0 && tid == 0) {
        int s = 0;
        for (int i = 0; i < SCAN_BLOCKS; i++) { s += g_part[i]; g_part[i] = s; }
    }
    {
        int sub = gtid & 15;
        int e = gtid >> 4;
        int s = 0, d = 0;
        if (e < NE) { s = ei[e]; d = ei[NE + e]; }
        while (e < NE) {
            float4 a = *(const float4*)(g_hn + s * DD + sub * 4);
            float4 c = *(const float4*)(g_hn + d * DD + sub * 4);
            int en = e + ESTRIDE;
            int s2 = 0, d2 = 0;
            if (en < NE) { s2 = ei[en]; d2 = ei[NE + en]; }   // prefetch
            float p = a.x * c.x + a.y * c.y + a.z * c.z + a.w * c.w;
#pragma unroll
            for (int o = 8; o; o >>= 1) p += __shfl_xor_sync(0xffffffffu, p, o);
            if (sub == 0) {
                float w = fmaxf(p, 0.0f);
                ew_out[e] = w;
                atomicAdd(&g_deg[d], w);
            }
            e = en; s = s2; d = d2;
        }
    }
    gsync();

    // ---- Phase 5: finalize offsets/cursors + dis --------------------------
    for (int n = gtid; n < NN; n += GT) {
        int bs = n >> 10;
        int base = bs ? g_part[bs - 1] : 0;
        int off = g_off[n] - g_cnt[n] + base;
        g_off[n] = off;
        g_cur[n] = off;
        g_dis[n] = rsqrtf(fmaxf(g_deg[n], EPSF));
    }
    gsync();

    // ---- Phase 6: scatter edges into CSR with FINAL normalized weight -----
    for (int e = gtid; e < NE; e += GT) {
        int s = ei[e];
        int d = ei[NE + e];
        float nw = g_dis[s] * ew_out[e] * g_dis[d];
        int pos = atomicAdd(&g_cur[d], 1);
        g_csr[pos] = make_int2(s, __float_as_int(nw));
    }
    gsync();

    // ---- Phase 7..11: K propagation steps ---------------------------------
    const float a = *alpha_p;
    const float* fin = g_f;
    for (int it = 0; it < K_ITERS; it++) {
        float* fout = (it == K_ITERS - 1) ? out : ((it & 1) ? g_f : g_f2);
        int n = gtid;                 // GT > NN: at most one node per thread
        if (n < NN) {
            float dis = g_dis[n];
            float acc = fin[n] * dis * dis;
            int beg = g_off[n];
            int end = beg + g_cnt[n];
            for (int j = beg; j < end; j++) {
                int2 p = g_csr[j];
                acc = fmaf(__int_as_float(p.y), __ldg(&fin[p.x]), acc);
            }
            fout[n] = (1.0f - a) * acc + a * g_f0[n];
        }
        gsync();
        fin = fout;
    }
}

// ---------------------------------------------------------------------------
extern "C" void kernel_launch(void* const* d_in, const int* in_sizes, int n_in,
                              void* d_out, int out_size) {
    const float* x = (const float*)d_in[0];
    const float* mask = (const float*)d_in[1];
    const int* ei = (const int*)d_in[2];
    const float* W = (const float*)d_in[3];
    const float* b = (const float*)d_in[4];
    const float* alpha = (const float*)d_in[5];
    float* out = (float*)d_out;              // [0, NN): f, [NN, NN+NE): edge_weights
    float* ew_out = out + NN;

    k_mega<<<GRID, TPB>>>(x, mask, ei, W, b, alpha, out, ew_out);
}

// round 15
// speedup vs baseline: 1.2948x; 1.2915x over previous
#include <cuda_runtime.h>
#include <cuda_bf16.h>

#define NN 100000
#define NE 1250000
#define DD 64
#define K_ITERS 5
#define EPSF 1e-8f

#define FEAT_BLOCKS 3125       // NN/32
#define CNT_BLOCKS  4883      // ceil(NE/256)
#define INIT_BLOCKS 391       // ceil(NN/256)

#define GRID 148
#define TPB 704               // 22 warps
#define GT (GRID * TPB)       // 104192 >= NN
#define NCHUNK 143            // ceil(NN / TPB)

// Scratch (device globals — allocation-free). cnt/deg rely on zero-init at
// module load and are reset to 0 at the end of every call (deterministic).
__device__ __align__(16) float g_hn[NN * DD];
__device__ float g_deg[NN];    // EXTRA degree (self loop added at read: 1+deg)
__device__ float g_dis[NN];
__device__ float g_f[NN];
__device__ float g_f2[NN];
__device__ float g_f0[NN];
__device__ int   g_cnt[NN];
__device__ int   g_off[NN];
__device__ int   g_cur[NN];
__device__ int   g_part[NCHUNK];
__device__ __align__(8) int2 g_csr[NE];  // .x = src, .y = float bits of normalized weight
__device__ unsigned g_bar_count;
__device__ unsigned g_bar_gen;

// ---------------------------------------------------------------------------
// Software grid barrier (148 blocks, all co-resident).
// ---------------------------------------------------------------------------
__device__ __forceinline__ void gsync() {
    __syncthreads();
    if (threadIdx.x == 0) {
        unsigned gen = atomicAdd(&g_bar_gen, 0u);
        __threadfence();
        unsigned t = atomicAdd(&g_bar_count, 1u);
        if (t == GRID - 1) {
            atomicExch(&g_bar_count, 0u);
            __threadfence();
            atomicAdd(&g_bar_gen, 1u);
        } else {
            while (atomicAdd(&g_bar_gen, 0u) == gen) __nanosleep(64);
        }
        __threadfence();
    }
    __syncthreads();
}

// ---------------------------------------------------------------------------
// Launch 1 (heterogeneous): feat | in-degree count | f0 init. All independent.
// ---------------------------------------------------------------------------
__global__ void k_feat_cnt_init(const float* __restrict__ x, const float* __restrict__ W,
                                const float* __restrict__ b, const int* __restrict__ ei,
                                const float* __restrict__ mask) {
    if (blockIdx.x >= FEAT_BLOCKS + CNT_BLOCKS) {
        int n = (blockIdx.x - FEAT_BLOCKS - CNT_BLOCKS) * 256 + threadIdx.x;
        if (n < NN) {
            float f0 = fmaxf(mask[n], 0.0f);
            g_f0[n] = f0;
            g_f[n]  = f0;
        }
        return;
    }
    if (blockIdx.x >= FEAT_BLOCKS) {
        int e = (blockIdx.x - FEAT_BLOCKS) * 256 + threadIdx.x;
        if (e < NE) atomicAdd(&g_cnt[ei[NE + e]], 1);
        return;
    }

    __shared__ float Wt[DD][DD + 1];
    __shared__ float xs[32][DD];
    __shared__ float bs[DD];

    int tid = threadIdx.x;
    int row0 = blockIdx.x * 32;

    for (int i = tid; i < DD * DD; i += 256) {
        int j = i >> 6, k = i & 63;
        Wt[k][j] = W[i];
    }
    if (tid < DD) bs[tid] = b[tid];
    for (int i = tid; i < 32 * DD; i += 256) {
        int r = i >> 6, k = i & 63;
        xs[r][k] = x[(row0 + r) * DD + k];
    }
    __syncthreads();

    int warp = tid >> 5, lane = tid & 31;
    int rbase = warp * 4;

    float acc[4][2];
#pragma unroll
    for (int r = 0; r < 4; r++) {
        acc[r][0] = bs[lane];
        acc[r][1] = bs[lane + 32];
    }
#pragma unroll 8
    for (int k = 0; k < DD; k++) {
        float w0 = Wt[k][lane];
        float w1 = Wt[k][lane + 32];
#pragma unroll
        for (int r = 0; r < 4; r++) {
            float xv = xs[rbase + r][k];
            acc[r][0] = fmaf(xv, w0, acc[r][0]);
            acc[r][1] = fmaf(xv, w1, acc[r][1]);
        }
    }
#pragma unroll
    for (int r = 0; r < 4; r++) {
        int n = row0 + rbase + r;
        float a0 = tanhf(acc[r][0]);
        float a1 = tanhf(acc[r][1]);
        float ss = a0 * a0 + a1 * a1;
#pragma unroll
        for (int o = 16; o; o >>= 1) ss += __shfl_xor_sync(0xffffffffu, ss, o);
        float inv = 1.0f / fmaxf(sqrtf(ss), EPSF);
        g_hn[n * DD + lane]      = a0 * inv;
        g_hn[n * DD + lane + 32] = a1 * inv;
    }
}

// ---------------------------------------------------------------------------
// Launch 2: flat edge cosines (16 lanes/edge) — R9's high-occupancy form.
// ---------------------------------------------------------------------------
__global__ void k_edge(const int* __restrict__ ei, float* __restrict__ ew_out) {
    int t = blockIdx.x * blockDim.x + threadIdx.x;
    int e = t >> 4;
    int sub = t & 15;
    if (e >= NE) return;

    int s = ei[e];
    int d = ei[NE + e];

    float4 a = *(const float4*)(g_hn + s * DD + sub * 4);
    float4 c = *(const float4*)(g_hn + d * DD + sub * 4);
    float p = a.x * c.x + a.y * c.y + a.z * c.z + a.w * c.w;
#pragma unroll
    for (int o = 8; o; o >>= 1) p += __shfl_xor_sync(0xffffffffu, p, o);

    if (sub == 0) {
        float w = fmaxf(p, 0.0f);
        ew_out[e] = w;
        atomicAdd(&g_deg[d], w);
    }
}

// ---------------------------------------------------------------------------
// Launch 3 (persistent): scan+dis -> offsets -> scatter(nw) -> 5x prop -> reset.
// ---------------------------------------------------------------------------
__global__ void __launch_bounds__(TPB, 1)
k_build_prop(const int* __restrict__ ei, const float* __restrict__ ew,
             const float* __restrict__ alpha_p, float* __restrict__ out) {
    __shared__ int ssc[TPB];
    __shared__ float sbase_f;   // unused placeholder alignment
    __shared__ int sbase;

    const int tid  = threadIdx.x;
    const int gtid = blockIdx.x * TPB + tid;
    const int chunk = blockIdx.x;            // one chunk per block (NCHUNK <= GRID)
    const int n_ch = chunk * TPB + tid;      // node handled in scan phases

    // ---- Phase A: local inclusive scan of cnt + dis ----
    int v = 0;
    if (chunk < NCHUNK) {
        v = (n_ch < NN) ? g_cnt[n_ch] : 0;
        ssc[tid] = v;
        __syncthreads();
        for (int o = 1; o < TPB; o <<= 1) {
            int u = (tid >= o) ? ssc[tid - o] : 0;
            __syncthreads();
            ssc[tid] += (tid >= o) ? u : 0;
            __syncthreads();
        }
        if (n_ch < NN) {
            g_off[n_ch] = ssc[tid];                  // inclusive, chunk-local
            g_dis[n_ch] = rsqrtf(fmaxf(1.0f + g_deg[n_ch], EPSF));
        }
        if (tid == TPB - 1) g_part[chunk] = ssc[tid];
    }
    gsync();

    // ---- Phase B: finalize offsets (base = sum of earlier chunk totals) ----
    if (chunk < NCHUNK) {
        if (tid == 0) {
            int s = 0;
            for (int i = 0; i < chunk; i++) s += g_part[i];
            sbase = s;
        }
        __syncthreads();
        if (n_ch < NN) {
            int off = g_off[n_ch] - v + sbase;       // exclusive + global base
            g_off[n_ch] = off;
            g_cur[n_ch] = off;
        }
    }
    gsync();

    // ---- Phase C: scatter with final normalized weight ----
    for (int e = gtid; e < NE; e += GT) {
        int s = ei[e];
        int d = ei[NE + e];
        float nw = g_dis[s] * ew[e] * g_dis[d];
        int pos = atomicAdd(&g_cur[d], 1);
        g_csr[pos] = make_int2(s, __float_as_int(nw));
    }
    gsync();

    // ---- Phase D: K propagation steps ----
    const float a = *alpha_p;
    const float* fin = g_f;
    const int n = gtid;            // GT >= NN: at most one node per thread
    for (int it = 0; it < K_ITERS; it++) {
        float* fout = (it == K_ITERS - 1) ? out : ((it & 1) ? g_f : g_f2);
        if (n < NN) {
            float dis = g_dis[n];
            float acc = fin[n] * dis * dis;
            int beg = g_off[n];
            int end = beg + g_cnt[n];
            for (int j = beg; j < end; j++) {
                int2 p = g_csr[j];
                acc = fmaf(__int_as_float(p.y), __ldg(&fin[p.x]), acc);
            }
            fout[n] = (1.0f - a) * acc + a * g_f0[n];
        }
        if (it < K_ITERS - 1) gsync();
        fin = fout;
    }

    // ---- Reset cnt/deg for next call (no barrier needed; next use is next launch) ----
    if (n < NN) {
        g_cnt[n] = 0;
        g_deg[n] = 0.0f;
    }
    (void)sbase_f;
}

// ---------------------------------------------------------------------------
extern "C" void kernel_launch(void* const* d_in, const int* in_sizes, int n_in,
                              void* d_out, int out_size) {
    const float* x = (const float*)d_in[0];
    const float* mask = (const float*)d_in[1];
    const int* ei = (const int*)d_in[2];
    const float* W = (const float*)d_in[3];
    const float* b = (const float*)d_in[4];
    const float* alpha = (const float*)d_in[5];
    float* out = (float*)d_out;              // [0, NN): f, [NN, NN+NE): edge_weights
    float* ew_out = out + NN;

    k_feat_cnt_init<<<FEAT_BLOCKS + CNT_BLOCKS + INIT_BLOCKS, 256>>>(x, W, b, ei, mask);
    k_edge<<<(NE * 16) / 256, 256>>>(ei, ew_out);
    k_build_prop<<<GRID, TPB>>>(ei, ew_out, alpha, out);
}

// round 16
// speedup vs baseline: 1.5679x; 1.2109x over previous
#include <cuda_runtime.h>
#include <cuda_bf16.h>
#include <cuda_fp16.h>

#define NN 100000
#define NE 1250000
#define DD 64
#define K_ITERS 5
#define EPSF 1e-8f

#define FEAT_BLOCKS 3125       // NN/32
#define CNT_BLOCKS  4883      // ceil(NE/256)
#define INIT_BLOCKS 391       // ceil(NN/256)

#define GRID 148
#define TPB 704               // 22 warps
#define GT (GRID * TPB)       // 104192 >= NN
#define NCHUNK 143            // ceil(NN / TPB)

// Scratch (device globals — allocation-free). cnt/deg rely on zero-init at
// module load and are reset to 0 at the end of every call (deterministic).
// Features stored as half2 in PERMUTED column order (dot is perm-invariant):
// slot l of row n holds columns (l, l+32).
__device__ __align__(16) __half2 g_hh[NN * 32];
__device__ float g_deg[NN];    // EXTRA degree (self loop added at read: 1+deg)
__device__ float g_dis[NN];
__device__ float g_f[NN];
__device__ float g_f2[NN];
__device__ float g_f0[NN];
__device__ int   g_cnt[NN];
__device__ int   g_off[NN];
__device__ int   g_cur[NN];
__device__ int   g_part[NCHUNK];
__device__ __align__(8) int2 g_csr[NE];  // .x = src, .y = float bits of normalized weight
__device__ unsigned g_bar_count;
__device__ unsigned g_bar_gen;

// ---------------------------------------------------------------------------
// Software grid barrier (148 blocks, all co-resident).
// ---------------------------------------------------------------------------
__device__ __forceinline__ void gsync() {
    __syncthreads();
    if (threadIdx.x == 0) {
        unsigned gen = atomicAdd(&g_bar_gen, 0u);
        __threadfence();
        unsigned t = atomicAdd(&g_bar_count, 1u);
        if (t == GRID - 1) {
            atomicExch(&g_bar_count, 0u);
            __threadfence();
            atomicAdd(&g_bar_gen, 1u);
        } else {
            while (atomicAdd(&g_bar_gen, 0u) == gen) __nanosleep(64);
        }
        __threadfence();
    }
    __syncthreads();
}

// ---------------------------------------------------------------------------
// Launch 1 (heterogeneous): feat | in-degree count | f0 init. All independent.
// Feat: W row-major in smem, rows padded to 68 floats -> conflict-free LDS.128
// (bank base 4*lane per quarter-warp). x rows read as float4 broadcasts.
// ---------------------------------------------------------------------------
__global__ void k_feat_cnt_init(const float* __restrict__ x, const float* __restrict__ W,
                                const float* __restrict__ b, const int* __restrict__ ei,
                                const float* __restrict__ mask) {
    if (blockIdx.x >= FEAT_BLOCKS + CNT_BLOCKS) {
        int n = (blockIdx.x - FEAT_BLOCKS - CNT_BLOCKS) * 256 + threadIdx.x;
        if (n < NN) {
            float f0 = fmaxf(mask[n], 0.0f);
            g_f0[n] = f0;
            g_f[n]  = f0;
        }
        return;
    }
    if (blockIdx.x >= FEAT_BLOCKS) {
        int e = (blockIdx.x - FEAT_BLOCKS) * 256 + threadIdx.x;
        if (e < NE) atomicAdd(&g_cnt[ei[NE + e]], 1);
        return;
    }

    __shared__ __align__(16) float Ws[DD][68];   // W[j][k], padded stride 68
    __shared__ __align__(16) float xs[32][DD];
    __shared__ float bs[DD];

    int tid = threadIdx.x;
    int row0 = blockIdx.x * 32;

    for (int i = tid; i < DD * DD; i += 256) {
        int j = i >> 6, k = i & 63;
        Ws[j][k] = W[i];                       // coalesced GMEM read
    }
    if (tid < DD) bs[tid] = b[tid];
    for (int i = tid; i < 32 * DD; i += 256) {
        int r = i >> 6, k = i & 63;
        xs[r][k] = x[(row0 + r) * DD + k];
    }
    __syncthreads();

    int warp = tid >> 5, lane = tid & 31;
    int rbase = warp * 4;

    float acc[4][2];
#pragma unroll
    for (int r = 0; r < 4; r++) {
        acc[r][0] = bs[lane];
        acc[r][1] = bs[lane + 32];
    }

#pragma unroll
    for (int k = 0; k < DD; k += 4) {
        float4 w0 = *(const float4*)&Ws[lane][k];
        float4 w1 = *(const float4*)&Ws[lane + 32][k];
#pragma unroll
        for (int r = 0; r < 4; r++) {
            float4 xv = *(const float4*)&xs[rbase + r][k];
            acc[r][0] = fmaf(xv.x, w0.x, acc[r][0]);
            acc[r][0] = fmaf(xv.y, w0.y, acc[r][0]);
            acc[r][0] = fmaf(xv.z, w0.z, acc[r][0]);
            acc[r][0] = fmaf(xv.w, w0.w, acc[r][0]);
            acc[r][1] = fmaf(xv.x, w1.x, acc[r][1]);
            acc[r][1] = fmaf(xv.y, w1.y, acc[r][1]);
            acc[r][1] = fmaf(xv.z, w1.z, acc[r][1]);
            acc[r][1] = fmaf(xv.w, w1.w, acc[r][1]);
        }
    }

#pragma unroll
    for (int r = 0; r < 4; r++) {
        int n = row0 + rbase + r;
        float a0 = tanhf(acc[r][0]);
        float a1 = tanhf(acc[r][1]);
        float ss = a0 * a0 + a1 * a1;
#pragma unroll
        for (int o = 16; o; o >>= 1) ss += __shfl_xor_sync(0xffffffffu, ss, o);
        float inv = 1.0f / fmaxf(sqrtf(ss), EPSF);
        // permuted-pair store: slot lane = (col lane, col lane+32)
        g_hh[n * 32 + lane] = __floats2half2_rn(a0 * inv, a1 * inv);
    }
}

// ---------------------------------------------------------------------------
// Launch 2: flat edge cosines, fp16 features, 8 lanes/edge (uint4 = 8 halves).
// fp32 accumulation; row = 128B = 1 L2 line per node.
// ---------------------------------------------------------------------------
__global__ void k_edge(const int* __restrict__ ei, float* __restrict__ ew_out) {
    int t = blockIdx.x * blockDim.x + threadIdx.x;
    int e = t >> 3;
    int sub = t & 7;
    if (e >= NE) return;

    int s = ei[e];
    int d = ei[NE + e];

    uint4 a = ((const uint4*)(g_hh + s * 32))[sub];
    uint4 c = ((const uint4*)(g_hh + d * 32))[sub];

    float p = 0.0f;
    {
        float2 fa, fc;
        fa = __half22float2(*(const __half2*)&a.x); fc = __half22float2(*(const __half2*)&c.x);
        p = fmaf(fa.x, fc.x, p); p = fmaf(fa.y, fc.y, p);
        fa = __half22float2(*(const __half2*)&a.y); fc = __half22float2(*(const __half2*)&c.y);
        p = fmaf(fa.x, fc.x, p); p = fmaf(fa.y, fc.y, p);
        fa = __half22float2(*(const __half2*)&a.z); fc = __half22float2(*(const __half2*)&c.z);
        p = fmaf(fa.x, fc.x, p); p = fmaf(fa.y, fc.y, p);
        fa = __half22float2(*(const __half2*)&a.w); fc = __half22float2(*(const __half2*)&c.w);
        p = fmaf(fa.x, fc.x, p); p = fmaf(fa.y, fc.y, p);
    }
#pragma unroll
    for (int o = 4; o; o >>= 1) p += __shfl_xor_sync(0xffffffffu, p, o);

    if (sub == 0) {
        float w = fmaxf(p, 0.0f);
        ew_out[e] = w;
        atomicAdd(&g_deg[d], w);
    }
}

// ---------------------------------------------------------------------------
// Launch 3 (persistent): scan+dis -> offsets -> scatter(nw) -> 5x prop -> reset.
// ---------------------------------------------------------------------------
__global__ void __launch_bounds__(TPB, 1)
k_build_prop(const int* __restrict__ ei, const float* __restrict__ ew,
             const float* __restrict__ alpha_p, float* __restrict__ out) {
    __shared__ int ssc[TPB];
    __shared__ int sbase;

    const int tid  = threadIdx.x;
    const int gtid = blockIdx.x * TPB + tid;
    const int chunk = blockIdx.x;            // one chunk per block (NCHUNK <= GRID)
    const int n_ch = chunk * TPB + tid;

    // ---- Phase A: local inclusive scan of cnt + dis ----
    int v = 0;
    if (chunk < NCHUNK) {
        v = (n_ch < NN) ? g_cnt[n_ch] : 0;
        ssc[tid] = v;
        __syncthreads();
        for (int o = 1; o < TPB; o <<= 1) {
            int u = (tid >= o) ? ssc[tid - o] : 0;
            __syncthreads();
            ssc[tid] += (tid >= o) ? u : 0;
            __syncthreads();
        }
        if (n_ch < NN) {
            g_off[n_ch] = ssc[tid];
            g_dis[n_ch] = rsqrtf(fmaxf(1.0f + g_deg[n_ch], EPSF));
        }
        if (tid == TPB - 1) g_part[chunk] = ssc[tid];
    }
    gsync();

    // ---- Phase B: finalize offsets ----
    if (chunk < NCHUNK) {
        if (tid == 0) {
            int s = 0;
            for (int i = 0; i < chunk; i++) s += g_part[i];
            sbase = s;
        }
        __syncthreads();
        if (n_ch < NN) {
            int off = g_off[n_ch] - v + sbase;
            g_off[n_ch] = off;
            g_cur[n_ch] = off;
        }
    }
    gsync();

    // ---- Phase C: scatter with final normalized weight ----
    for (int e = gtid; e < NE; e += GT) {
        int s = ei[e];
        int d = ei[NE + e];
        float nw = g_dis[s] * ew[e] * g_dis[d];
        int pos = atomicAdd(&g_cur[d], 1);
        g_csr[pos] = make_int2(s, __float_as_int(nw));
    }
    gsync();

    // ---- Phase D: K propagation steps ----
    const float a = *alpha_p;
    const float* fin = g_f;
    const int n = gtid;
    for (int it = 0; it < K_ITERS; it++) {
        float* fout = (it == K_ITERS - 1) ? out : ((it & 1) ? g_f : g_f2);
        if (n < NN) {
            float dis = g_dis[n];
            float acc = fin[n] * dis * dis;
            int beg = g_off[n];
            int end = beg + g_cnt[n];
            for (int j = beg; j < end; j++) {
                int2 p = g_csr[j];
                acc = fmaf(__int_as_float(p.y), __ldg(&fin[p.x]), acc);
            }
            fout[n] = (1.0f - a) * acc + a * g_f0[n];
        }
        if (it < K_ITERS - 1) gsync();
        fin = fout;
    }

    // ---- Reset cnt/deg for next call ----
    if (n < NN) {
        g_cnt[n] = 0;
        g_deg[n] = 0.0f;
    }
}

// ---------------------------------------------------------------------------
extern "C" void kernel_launch(void* const* d_in, const int* in_sizes, int n_in,
                              void* d_out, int out_size) {
    const float* x = (const float*)d_in[0];
    const float* mask = (const float*)d_in[1];
    const int* ei = (const int*)d_in[2];
    const float* W = (const float*)d_in[3];
    const float* b = (const float*)d_in[4];
    const float* alpha = (const float*)d_in[5];
    float* out = (float*)d_out;              // [0, NN): f, [NN, NN+NE): edge_weights
    float* ew_out = out + NN;

    k_feat_cnt_init<<<FEAT_BLOCKS + CNT_BLOCKS + INIT_BLOCKS, 256>>>(x, W, b, ei, mask);
    k_edge<<<(NE * 8 + 255) / 256, 256>>>(ei, ew_out);
    k_build_prop<<<GRID, TPB>>>(ei, ew_out, alpha, out);
}